// round 5
// baseline (speedup 1.0000x reference)
#include <cuda_runtime.h>
#include <cstdint>

// Problem constants
#define BATCH   32
#define CIN     1024
#define HH      37
#define WW      37
#define DIM     512
#define COUT    120
#define HW      (HH * WW)                 // 1369
#define CHW     (CIN * HW)                // 1401856
#define M1      (BATCH * HW)              // 43808
#define K1      (CIN * 9)                 // 9216
#define NT1     (K1 / 8)                  // 1152 k-tiles for conv1

// Intermediate activations in NHWC-flattened layout: g_mid[pos][512]
// 43808 * 512 floats = 89.7 MB static device scratch (allocation-guard safe).
__device__ float g_mid[(size_t)M1 * DIM];

// ---------------------------------------------------------------------------
// Kernel 1: conv3x3 (1024->512, pad 1) + bias + ReLU6 as implicit GEMM.
// M = 43808 positions, N = 512 out-channels, K = 9216 (cin*3*3).
// Block tile 128x128, BK=8, 256 threads, 8x8 per-thread tile (4+4 split at 64).
// Register-staged gmem->smem pipeline (prefetch next tile during compute).
// ---------------------------------------------------------------------------
__global__ __launch_bounds__(256, 2)
void conv3x3_relu6_kernel(const float* __restrict__ fmap,
                          const float* __restrict__ w1,
                          const float* __restrict__ b1)
{
    __shared__ float As[8][128];   // [k][m]
    __shared__ float Bs[8][128];   // [k][n]

    const int tid    = threadIdx.x;
    const int m_base = blockIdx.x * 128;
    const int n_base = blockIdx.y * 128;

    // ---- A (im2col) loader mapping: each thread loads 4 elems, fixed k ----
    const int a_k = tid >> 5;          // 0..7  (k within tile; constant per warp)
    const int a_m = tid & 31;          // m_local = a_m + j*32

    int  pbase[4];
    int  ohv[4], owv[4];
    bool mval[4];
#pragma unroll
    for (int j = 0; j < 4; ++j) {
        int m   = m_base + a_m + j * 32;
        mval[j] = (m < M1);
        int mm  = mval[j] ? m : 0;
        int b   = mm / HW;
        int rem = mm - b * HW;
        int oh  = rem / WW;
        int ow  = rem - oh * WW;
        ohv[j]  = oh;
        owv[j]  = ow;
        // final addr = pbase + ci*HW + r*37 + s  (includes -37-1 for pad offset)
        pbase[j] = b * CHW + oh * WW + ow - (WW + 1);
    }

    // ---- B loader mapping: float4 of w1 per thread ----
    const int b_n = tid >> 1;              // 0..127
    const int b_k = (tid & 1) * 4;         // 0 or 4
    const float* w1p = w1 + (size_t)(n_base + b_n) * K1 + b_k;

    // ---- compute mapping ----
    const int ty = tid >> 4;   // 0..15 -> rows ty*4 and 64+ty*4
    const int tx = tid & 15;   // 0..15 -> cols tx*4 and 64+tx*4

    float acc[8][8];
#pragma unroll
    for (int i = 0; i < 8; ++i)
#pragma unroll
        for (int j = 0; j < 8; ++j) acc[i][j] = 0.f;

    float  ar[4];
    float4 br;

    // register-staged tile loader
    auto load_tile = [&](int kt) {
        int kk = kt * 8 + a_k;
        int ci = kk / 9;
        int rs = kk - ci * 9;
        int r  = rs / 3;
        int s  = rs - r * 3;
        int offk = ci * HW + r * WW + s;
#pragma unroll
        for (int j = 0; j < 4; ++j) {
            int ih = ohv[j] + r - 1;
            int iw = owv[j] + s - 1;
            bool ok = mval[j] && ((unsigned)ih < (unsigned)HH)
                              && ((unsigned)iw < (unsigned)WW);
            ar[j] = ok ? __ldg(fmap + pbase[j] + offk) : 0.f;
        }
        br = *reinterpret_cast<const float4*>(w1p + (size_t)kt * 8);
    };

    load_tile(0);

    for (int kt = 0; kt < NT1; ++kt) {
        // stage regs -> smem
#pragma unroll
        for (int j = 0; j < 4; ++j)
            As[a_k][a_m + j * 32] = ar[j];
        Bs[b_k + 0][b_n] = br.x;
        Bs[b_k + 1][b_n] = br.y;
        Bs[b_k + 2][b_n] = br.z;
        Bs[b_k + 3][b_n] = br.w;
        __syncthreads();

        // prefetch next tile (LDG latency hidden behind compute below)
        if (kt + 1 < NT1) load_tile(kt + 1);

#pragma unroll
        for (int kk = 0; kk < 8; ++kk) {
            float4 a0 = *reinterpret_cast<const float4*>(&As[kk][ty * 4]);
            float4 a1 = *reinterpret_cast<const float4*>(&As[kk][64 + ty * 4]);
            float4 b0 = *reinterpret_cast<const float4*>(&Bs[kk][tx * 4]);
            float4 b1v = *reinterpret_cast<const float4*>(&Bs[kk][64 + tx * 4]);
            float av[8] = {a0.x, a0.y, a0.z, a0.w, a1.x, a1.y, a1.z, a1.w};
            float bv[8] = {b0.x, b0.y, b0.z, b0.w, b1v.x, b1v.y, b1v.z, b1v.w};
#pragma unroll
            for (int i = 0; i < 8; ++i)
#pragma unroll
                for (int j = 0; j < 8; ++j)
                    acc[i][j] = fmaf(av[i], bv[j], acc[i][j]);
        }
        __syncthreads();
    }

    // epilogue: bias + ReLU6, store to g_mid[m][n] (NHWC rows of 512)
    float bias0[4], bias1[4];
#pragma unroll
    for (int c = 0; c < 4; ++c) {
        bias0[c] = __ldg(b1 + n_base + tx * 4 + c);
        bias1[c] = __ldg(b1 + n_base + 64 + tx * 4 + c);
    }

#pragma unroll
    for (int ri = 0; ri < 8; ++ri) {
        int row_local = (ri < 4) ? (ty * 4 + ri) : (64 + ty * 4 + (ri - 4));
        int m = m_base + row_local;
        if (m >= M1) continue;
        float* outp = &g_mid[(size_t)m * DIM + n_base];

        float4 v0, v1;
        float* pv0 = reinterpret_cast<float*>(&v0);
        float* pv1 = reinterpret_cast<float*>(&v1);
#pragma unroll
        for (int c = 0; c < 4; ++c) {
            float x0 = acc[ri][c]     + bias0[c];
            float x1 = acc[ri][4 + c] + bias1[c];
            pv0[c] = fminf(fmaxf(x0, 0.f), 6.f);
            pv1[c] = fminf(fmaxf(x1, 0.f), 6.f);
        }
        *reinterpret_cast<float4*>(outp + tx * 4)      = v0;
        *reinterpret_cast<float4*>(outp + 64 + tx * 4) = v1;
    }
}

// ---------------------------------------------------------------------------
// Kernel 2: conv1x1 (512->120) + bias. GEMM M=43808, N=120(pad 128), K=512.
// Output row-major [pos][120] == NHWC reshape (B,H,W,A,6) -> transpose is free.
// ---------------------------------------------------------------------------
__global__ __launch_bounds__(256)
void conv1x1_kernel(const float* __restrict__ w2,
                    const float* __restrict__ b2,
                    float* __restrict__ out)
{
    __shared__ float As[16][64];    // [k][pos]
    __shared__ float Bs[16][128];   // [k][co]

    const int tid    = threadIdx.x;
    const int m_base = blockIdx.x * 64;

    // A loader: pos_local = tid>>2, kq = (tid&3)*4
    const int a_p  = tid >> 2;
    const int a_kq = (tid & 3) * 4;
    const int a_m  = m_base + a_p;
    const bool a_ok = (a_m < M1);

    // B loader: co = tid>>1 (guard <120), kq = (tid&1)*8 (two float4s)
    const int b_co = tid >> 1;
    const int b_kq = (tid & 1) * 8;
    const bool b_ok = (b_co < COUT);

    const int ty = tid >> 4;   // 0..15 -> rows ty*4..+3
    const int tx = tid & 15;   // 0..15 -> cols tx*4 and 64+tx*4

    float acc[4][8];
#pragma unroll
    for (int i = 0; i < 4; ++i)
#pragma unroll
        for (int j = 0; j < 8; ++j) acc[i][j] = 0.f;

    for (int kt = 0; kt < DIM / 16; ++kt) {
        // load A tile
        float4 av = make_float4(0.f, 0.f, 0.f, 0.f);
        if (a_ok)
            av = *reinterpret_cast<const float4*>(
                     &g_mid[(size_t)a_m * DIM + kt * 16 + a_kq]);
        As[a_kq + 0][a_p] = av.x;
        As[a_kq + 1][a_p] = av.y;
        As[a_kq + 2][a_p] = av.z;
        As[a_kq + 3][a_p] = av.w;

        // load B tile
        float4 bv0 = make_float4(0.f, 0.f, 0.f, 0.f);
        float4 bv1 = make_float4(0.f, 0.f, 0.f, 0.f);
        if (b_ok) {
            const float* wp = w2 + (size_t)b_co * DIM + kt * 16 + b_kq;
            bv0 = *reinterpret_cast<const float4*>(wp);
            bv1 = *reinterpret_cast<const float4*>(wp + 4);
        }
        Bs[b_kq + 0][b_co] = bv0.x;
        Bs[b_kq + 1][b_co] = bv0.y;
        Bs[b_kq + 2][b_co] = bv0.z;
        Bs[b_kq + 3][b_co] = bv0.w;
        Bs[b_kq + 4][b_co] = bv1.x;
        Bs[b_kq + 5][b_co] = bv1.y;
        Bs[b_kq + 6][b_co] = bv1.z;
        Bs[b_kq + 7][b_co] = bv1.w;
        __syncthreads();

#pragma unroll
        for (int kk = 0; kk < 16; ++kk) {
            float4 a0 = *reinterpret_cast<const float4*>(&As[kk][ty * 4]);
            float4 b0 = *reinterpret_cast<const float4*>(&Bs[kk][tx * 4]);
            float4 b1v = *reinterpret_cast<const float4*>(&Bs[kk][64 + tx * 4]);
            float av4[4] = {a0.x, a0.y, a0.z, a0.w};
            float bv8[8] = {b0.x, b0.y, b0.z, b0.w, b1v.x, b1v.y, b1v.z, b1v.w};
#pragma unroll
            for (int i = 0; i < 4; ++i)
#pragma unroll
                for (int j = 0; j < 8; ++j)
                    acc[i][j] = fmaf(av4[i], bv8[j], acc[i][j]);
        }
        __syncthreads();
    }

    // epilogue: +bias, store to out[pos][120]
    float bias0[4], bias1[4];
#pragma unroll
    for (int c = 0; c < 4; ++c) {
        bias0[c] = __ldg(b2 + tx * 4 + c);                         // cols 0..63 always valid
        int n1 = 64 + tx * 4 + c;
        bias1[c] = (n1 < COUT) ? __ldg(b2 + n1) : 0.f;
    }
    const bool chunk1_ok = (64 + tx * 4 + 3) < COUT;               // tx < 14

#pragma unroll
    for (int i = 0; i < 4; ++i) {
        int m = m_base + ty * 4 + i;
        if (m >= M1) continue;
        float* op = out + (size_t)m * COUT;

        float4 v0;
        float* pv0 = reinterpret_cast<float*>(&v0);
#pragma unroll
        for (int c = 0; c < 4; ++c) pv0[c] = acc[i][c] + bias0[c];
        *reinterpret_cast<float4*>(op + tx * 4) = v0;

        if (chunk1_ok) {
            float4 v1;
            float* pv1 = reinterpret_cast<float*>(&v1);
#pragma unroll
            for (int c = 0; c < 4; ++c) pv1[c] = acc[i][4 + c] + bias1[c];
            *reinterpret_cast<float4*>(op + 64 + tx * 4) = v1;
        }
    }
}

// ---------------------------------------------------------------------------
// Launch: inputs in metadata order: fmap, w1, b1, w2, b2. Output fp32.
// ---------------------------------------------------------------------------
extern "C" void kernel_launch(void* const* d_in, const int* in_sizes, int n_in,
                              void* d_out, int out_size)
{
    const float* fmap = (const float*)d_in[0];
    const float* w1   = (const float*)d_in[1];
    const float* b1   = (const float*)d_in[2];
    const float* w2   = (const float*)d_in[3];
    const float* b2   = (const float*)d_in[4];
    float* out = (float*)d_out;

    dim3 grid1((M1 + 127) / 128, DIM / 128);   // (343, 4)
    conv3x3_relu6_kernel<<<grid1, 256>>>(fmap, w1, b1);

    dim3 grid2((M1 + 63) / 64);                // 685
    conv1x1_kernel<<<grid2, 256>>>(w2, b2, out);
}

// round 9
// speedup vs baseline: 5.6005x; 5.6005x over previous
#include <cuda_runtime.h>
#include <cuda_bf16.h>
#include <cstdint>

// ---------------------------------------------------------------------------
// Arch gate: tcgen05 only assembles under sm_103a-family targets. The
// compute_103 (no-'a') PTX pass gets a correct fp32 SIMT fallback.
// ---------------------------------------------------------------------------
#if defined(__CUDA_ARCH__) && (defined(__CUDA_ARCH_FEAT_SM103_ALL) || \
    defined(__CUDA_ARCH_FEAT_SM100_ALL) || defined(__CUDA_ARCH_FEAT_SM101_ALL))
#define TC05 1
#else
#define TC05 0
#endif

// ---------------------------------------------------------------------------
// Problem constants
// ---------------------------------------------------------------------------
#define BATCH   32
#define CIN     1024
#define HH      37
#define WW      37
#define DIM     512
#define COUT    120
#define HW      (HH * WW)                 // 1369
#define CHW     (CIN * HW)
#define M1      (BATCH * HW)              // 43808
#define K1      (CIN * 9)                 // 9216

// conv1 MMA tiling: 128M x 128N, BK=64 bf16, hi/lo split => 12 MMAs per tile
#define BM      128
#define BN      128
#define KTILES  144                        // 9 (r,s) * 16 ci-blocks of 64
// single smem stage (offsets, 1024-aligned)
#define AHI_OFF 0
#define ALO_OFF 16384
#define BHI_OFF 32768
#define BLO_OFF 49152
#define SMEM_DYN (65536 + 1024)

// idesc: kind::f16, bf16 x bf16 -> fp32, M=128, N=128, K-major both
#define IDESC 0x8200490u

// ---------------------------------------------------------------------------
// Device scratch (static: allocation-guard safe)
// ---------------------------------------------------------------------------
__device__ __align__(16) __nv_bfloat16 g_Ah[(size_t)M1 * CIN];   // fmap NHWC hi
__device__ __align__(16) __nv_bfloat16 g_Al[(size_t)M1 * CIN];   // fmap NHWC lo
__device__ __align__(16) __nv_bfloat16 g_Bh[(size_t)DIM * K1];   // w1 [co][rs][ci] hi
__device__ __align__(16) __nv_bfloat16 g_Bl[(size_t)DIM * K1];   // w1 [co][rs][ci] lo
__device__ __align__(16) float         g_mid[(size_t)M1 * DIM];  // conv1 out, NHWC

// ---------------------------------------------------------------------------
// PTX helpers
// ---------------------------------------------------------------------------
__device__ __forceinline__ uint32_t smem_u32(const void* p) {
    uint32_t a;
    asm("{ .reg .u64 t; cvta.to.shared.u64 t, %1; cvt.u32.u64 %0, t; }"
        : "=r"(a) : "l"(p));
    return a;
}

__device__ __forceinline__ uint32_t elect_one() {
    uint32_t pred;
    asm volatile(
        "{\n\t"
        ".reg .pred p;\n\t"
        "elect.sync _|p, 0xFFFFFFFF;\n\t"
        "selp.b32 %0, 1, 0, p;\n\t"
        "}" : "=r"(pred));
    return pred;
}

__device__ __forceinline__ void mbar_init(uint32_t a, uint32_t cnt) {
    asm volatile("mbarrier.init.shared.b64 [%0], %1;" :: "r"(a), "r"(cnt) : "memory");
}
__device__ __forceinline__ void mbar_inval(uint32_t a) {
    asm volatile("mbarrier.inval.shared.b64 [%0];" :: "r"(a) : "memory");
}
__device__ __forceinline__ void mbar_wait(uint32_t a, uint32_t parity) {
    asm volatile(
        "{\n\t"
        ".reg .pred P1;\n\t"
        "WAIT_LOOP_%=:\n\t"
        "mbarrier.try_wait.parity.acquire.cta.shared::cta.b64 P1, [%0], %1, 0x989680;\n\t"
        "@P1 bra.uni WAIT_DONE_%=;\n\t"
        "bra.uni WAIT_LOOP_%=;\n\t"
        "WAIT_DONE_%=:\n\t"
        "}"
        :: "r"(a), "r"(parity) : "memory");
}

#if TC05
// SW128 K-major descriptor: LBO=1, SBO=64, version=1, layout=2
__device__ __forceinline__ uint64_t sdesc(uint32_t addr) {
    return 0x4000404000010000ULL | (uint64_t)((addr >> 4) & 0x3FFF);
}

__device__ __forceinline__ void mma_f16_ss(uint32_t d, uint64_t ad, uint64_t bd,
                                           uint32_t en) {
    asm volatile(
        "{\n\t"
        ".reg .pred p;\n\t"
        "setp.ne.u32 p, %5, 0;\n\t"
        "tcgen05.mma.cta_group::1.kind::f16 [%0], %1, %2, %3, {%4, %4, %4, %4}, p;\n\t"
        "}"
        :: "r"(d), "l"(ad), "l"(bd), "r"(IDESC), "r"(0u), "r"(en) : "memory");
}

__device__ __forceinline__ void ldtm_x32(uint32_t* r, uint32_t tmem_addr) {
    asm volatile(
        "tcgen05.ld.sync.aligned.32x32b.x32.b32 "
        "{%0, %1, %2, %3, %4, %5, %6, %7, "
        " %8, %9, %10, %11, %12, %13, %14, %15, "
        " %16, %17, %18, %19, %20, %21, %22, %23, "
        " %24, %25, %26, %27, %28, %29, %30, %31}, [%32];"
        : "=r"(r[0]),  "=r"(r[1]),  "=r"(r[2]),  "=r"(r[3]),
          "=r"(r[4]),  "=r"(r[5]),  "=r"(r[6]),  "=r"(r[7]),
          "=r"(r[8]),  "=r"(r[9]),  "=r"(r[10]), "=r"(r[11]),
          "=r"(r[12]), "=r"(r[13]), "=r"(r[14]), "=r"(r[15]),
          "=r"(r[16]), "=r"(r[17]), "=r"(r[18]), "=r"(r[19]),
          "=r"(r[20]), "=r"(r[21]), "=r"(r[22]), "=r"(r[23]),
          "=r"(r[24]), "=r"(r[25]), "=r"(r[26]), "=r"(r[27]),
          "=r"(r[28]), "=r"(r[29]), "=r"(r[30]), "=r"(r[31])
        : "r"(tmem_addr));
}
#endif  // TC05

// ---------------------------------------------------------------------------
// Prep 1: fmap fp32 NCHW -> NHWC bf16 hi/lo (tiled smem transpose per batch)
// ---------------------------------------------------------------------------
__global__ void prep_fmap_kernel(const float* __restrict__ fmap) {
    __shared__ float tile[32][33];
    const int b    = blockIdx.z;
    const int pos0 = blockIdx.x * 32;
    const int ci0  = blockIdx.y * 32;
    const int tx = threadIdx.x, ty = threadIdx.y;   // 32 x 8

#pragma unroll
    for (int i = 0; i < 4; ++i) {
        int ci  = ci0 + ty + i * 8;
        int pos = pos0 + tx;
        float v = 0.f;
        if (pos < HW) v = fmap[(size_t)b * CHW + (size_t)ci * HW + pos];
        tile[ty + i * 8][tx] = v;
    }
    __syncthreads();
#pragma unroll
    for (int i = 0; i < 4; ++i) {
        int pos = pos0 + ty + i * 8;
        int ci  = ci0 + tx;
        if (pos < HW) {
            float x = tile[tx][ty + i * 8];
            __nv_bfloat16 h = __float2bfloat16(x);
            float hf = __bfloat162float(h);
            __nv_bfloat16 l = __float2bfloat16(x - hf);
            size_t o = ((size_t)b * HW + pos) * CIN + ci;
            g_Ah[o] = h;
            g_Al[o] = l;
        }
    }
}

// ---------------------------------------------------------------------------
// Prep 2: w1 [co][ci][rs] fp32 -> [co][rs][ci] bf16 hi/lo
// ---------------------------------------------------------------------------
__global__ void prep_w1_kernel(const float* __restrict__ w1) {
    int idx = blockIdx.x * 256 + threadIdx.x;
    if (idx >= DIM * 9 * CIN) return;
    int ci = idx & (CIN - 1);
    int t  = idx >> 10;
    int rs = t % 9;
    int co = t / 9;
    float x = w1[(size_t)co * K1 + ci * 9 + rs];
    __nv_bfloat16 h = __float2bfloat16(x);
    float hf = __bfloat162float(h);
    __nv_bfloat16 l = __float2bfloat16(x - hf);
    g_Bh[idx] = h;
    g_Bl[idx] = l;
}

// ---------------------------------------------------------------------------
// Kernel 1: conv3x3 + bias + ReLU6.
//   TC05 path : tcgen05 bf16 3-split implicit GEMM, 128x128 tile, BK=64.
//               SINGLE smem stage, SINGLE mbarrier, one commit per k-tile,
//               wait at end of the same iteration (example-proven structure).
//               Gmem->reg loads of tile kt+1 are issued before the wait, so
//               they overlap the MMA of tile kt. 2 CTAs/SM.
//   fallback  : proven fp32 SIMT implicit GEMM (round-5), same launch config.
// Grid (ceil(M1/128), 4), 256 threads, SMEM_DYN dynamic smem.
// ---------------------------------------------------------------------------
__global__ __launch_bounds__(256, 2)
void conv3x3_mma_kernel(const float* __restrict__ fmap,
                        const float* __restrict__ w1,
                        const float* __restrict__ b1)
{
#if TC05
    // ============================ tcgen05 path ============================
    extern __shared__ char dsm_raw[];
    __shared__ uint32_t s_tmem;
    __shared__ __align__(8) uint64_t s_mbar;

    char* dsm = (char*)((((uintptr_t)dsm_raw) + 1023) & ~(uintptr_t)1023);
    const uint32_t smbase = smem_u32(dsm);
    const uint32_t mb = smem_u32(&s_mbar);

    const int tid = threadIdx.x;
    const int wid = tid >> 5;

    if (wid == 0) {
        asm volatile(
            "tcgen05.alloc.cta_group::1.sync.aligned.shared::cta.b32 [%0], %1;"
            :: "r"(smem_u32(&s_tmem)), "r"(128u) : "memory");
        asm volatile("tcgen05.relinquish_alloc_permit.cta_group::1.sync.aligned;");
    }
    if (tid == 0) mbar_init(mb, 1);
    __syncthreads();
    const uint32_t tmem = s_tmem;

    // loader mapping: 8 lanes cover one 128B tile row; each thread owns
    // 4 A-rows and 4 B-rows (hi + lo each) => 16 x LDG.128 per k-tile.
    const int g  = tid >> 3;       // 0..31  (row group; rows g, g+32, g+64, g+96)
    const int gl = tid & 7;        // 16B chunk within row

    int  rbb[4], roh[4], row_[4];
    bool rmv[4];
#pragma unroll
    for (int i = 0; i < 4; ++i) {
        int row = g + i * 32;
        int m   = blockIdx.x * BM + row;
        rmv[i]  = (m < M1);
        int mm  = rmv[i] ? m : 0;
        rbb[i]  = mm / HW;
        int rem = mm - rbb[i] * HW;
        roh[i]  = rem / WW;
        row_[i] = rem - roh[i] * WW;
    }

    const int nbase = blockIdx.y * BN;

    uint4 vah[4], val_[4], vbh[4], vbl[4];

    // gather gmem -> regs for k-tile kt (high MLP, 16 independent LDG.128)
    auto load_regs = [&](int kt) {
        const int rs  = kt >> 4;
        const int cib = (kt & 15) << 6;
        const int r   = rs / 3;
        const int s   = rs - r * 3;
#pragma unroll
        for (int i = 0; i < 4; ++i) {
            int ih = roh[i] + r - 1;
            int iw = row_[i] + s - 1;
            uint4 vh = make_uint4(0u, 0u, 0u, 0u);
            uint4 vl = make_uint4(0u, 0u, 0u, 0u);
            if (rmv[i] && (unsigned)ih < (unsigned)HH && (unsigned)iw < (unsigned)WW) {
                size_t e = ((size_t)(rbb[i] * HH + ih) * WW + iw) * CIN + cib + gl * 8;
                vh = *reinterpret_cast<const uint4*>(g_Ah + e);
                vl = *reinterpret_cast<const uint4*>(g_Al + e);
            }
            vah[i] = vh;
            val_[i] = vl;
        }
#pragma unroll
        for (int i = 0; i < 4; ++i) {
            size_t e = (size_t)(nbase + g + i * 32) * K1 + (size_t)rs * CIN + cib + gl * 8;
            vbh[i] = *reinterpret_cast<const uint4*>(g_Bh + e);
            vbl[i] = *reinterpret_cast<const uint4*>(g_Bl + e);
        }
    };

    load_regs(0);

    for (int kt = 0; kt < KTILES; ++kt) {
        // -------- stores regs -> smem (SW128 swizzled). MMA(kt-1) already
        // completed (waited at end of previous iteration), so the single
        // stage is free for rewrite. --------
#pragma unroll
        for (int i = 0; i < 4; ++i) {
            uint32_t off = (g + i * 32) * 128 + gl * 16;
            uint32_t sw  = off ^ ((off >> 3) & 0x70);
            *reinterpret_cast<uint4*>(dsm + AHI_OFF + sw) = vah[i];
            *reinterpret_cast<uint4*>(dsm + ALO_OFF + sw) = val_[i];
            *reinterpret_cast<uint4*>(dsm + BHI_OFF + sw) = vbh[i];
            *reinterpret_cast<uint4*>(dsm + BLO_OFF + sw) = vbl[i];
        }
        asm volatile("fence.proxy.async.shared::cta;" ::: "memory");
        __syncthreads();

        // -------- MMA issue: warp 0, elected lane (example pattern) --------
        if (wid == 0) {
            if (elect_one()) {
                const uint64_t adh = sdesc(smbase + AHI_OFF);
                const uint64_t adl = sdesc(smbase + ALO_OFF);
                const uint64_t bdh = sdesc(smbase + BHI_OFF);
                const uint64_t bdl = sdesc(smbase + BLO_OFF);
#pragma unroll
                for (int ks = 0; ks < 4; ++ks) {
                    uint32_t en0 = (kt > 0 || ks > 0) ? 1u : 0u;
                    mma_f16_ss(tmem, adh + ks * 2, bdh + ks * 2, en0);  // hi*hi
                    mma_f16_ss(tmem, adl + ks * 2, bdh + ks * 2, 1u);   // lo*hi
                    mma_f16_ss(tmem, adh + ks * 2, bdl + ks * 2, 1u);   // hi*lo
                }
                asm volatile(
                    "tcgen05.commit.cta_group::1.mbarrier::arrive::one.shared::cluster.b64 [%0];"
                    :: "r"(mb) : "memory");
            }
        }

        // -------- prefetch next tile into regs: overlaps the MMA --------
        if (kt + 1 < KTILES) load_regs(kt + 1);

        // -------- wait for MMA(kt) before smem is rewritten next iter --------
        mbar_wait(mb, kt & 1);
    }

    asm volatile("tcgen05.fence::after_thread_sync;" ::: "memory");

    // -------- epilogue: TMEM -> bias+ReLU6 -> g_mid --------
    {
        const int lane = tid & 31;
        const int sub  = wid & 3;                // TMEM subpartition (rows)
        const int ch   = (wid >> 2) * 64;        // column half
        const int mrow = blockIdx.x * BM + sub * 32 + lane;
        const int nb0  = nbase + ch;
        float* outp = g_mid + (size_t)mrow * DIM + nb0;
        const bool mok = (mrow < M1);

#pragma unroll
        for (int cb = 0; cb < 64; cb += 32) {
            uint32_t regs[32];
            ldtm_x32(regs, tmem + ch + cb);
            asm volatile("tcgen05.wait::ld.sync.aligned;" ::: "memory");
            if (mok) {
#pragma unroll
                for (int q = 0; q < 8; ++q) {
                    float4 v;
                    float* pv = reinterpret_cast<float*>(&v);
#pragma unroll
                    for (int c = 0; c < 4; ++c) {
                        float x = __uint_as_float(regs[q * 4 + c])
                                + __ldg(b1 + nb0 + cb + q * 4 + c);
                        pv[c] = fminf(fmaxf(x, 0.f), 6.f);
                    }
                    *reinterpret_cast<float4*>(outp + cb + q * 4) = v;
                }
            }
        }
    }

    __syncthreads();
    if (tid == 0) mbar_inval(mb);
    __syncthreads();
    if (wid == 0) {
        asm volatile("tcgen05.dealloc.cta_group::1.sync.aligned.b32 %0, %1;"
                     :: "r"(tmem), "r"(128u));
    }

#else
    // ====================== fp32 SIMT fallback (round-5) ======================
    __shared__ float As[8][128];
    __shared__ float Bs[8][128];

    const int tid    = threadIdx.x;
    const int m_base = blockIdx.x * 128;
    const int n_base = blockIdx.y * 128;

    const int a_k = tid >> 5;
    const int a_m = tid & 31;

    int  pbase[4];
    int  ohv[4], owv[4];
    bool mval[4];
#pragma unroll
    for (int j = 0; j < 4; ++j) {
        int m   = m_base + a_m + j * 32;
        mval[j] = (m < M1);
        int mm  = mval[j] ? m : 0;
        int b   = mm / HW;
        int rem = mm - b * HW;
        int oh  = rem / WW;
        int ow  = rem - oh * WW;
        ohv[j]  = oh;
        owv[j]  = ow;
        pbase[j] = b * CHW + oh * WW + ow - (WW + 1);
    }

    const int b_n = tid >> 1;
    const int b_k = (tid & 1) * 4;
    const float* w1p = w1 + (size_t)(n_base + b_n) * K1 + b_k;

    const int ty = tid >> 4;
    const int tx = tid & 15;

    float acc[8][8];
#pragma unroll
    for (int i = 0; i < 8; ++i)
#pragma unroll
        for (int j = 0; j < 8; ++j) acc[i][j] = 0.f;

    float  ar[4];
    float4 br;

    auto load_tile = [&](int kt) {
        int kk = kt * 8 + a_k;
        int ci = kk / 9;
        int rs = kk - ci * 9;
        int r  = rs / 3;
        int s  = rs - r * 3;
        int offk = ci * HW + r * WW + s;
#pragma unroll
        for (int j = 0; j < 4; ++j) {
            int ih = ohv[j] + r - 1;
            int iw = owv[j] + s - 1;
            bool ok = mval[j] && ((unsigned)ih < (unsigned)HH)
                              && ((unsigned)iw < (unsigned)WW);
            ar[j] = ok ? __ldg(fmap + pbase[j] + offk) : 0.f;
        }
        br = *reinterpret_cast<const float4*>(w1p + (size_t)kt * 8);
    };

    load_tile(0);

    for (int kt = 0; kt < K1 / 8; ++kt) {
#pragma unroll
        for (int j = 0; j < 4; ++j)
            As[a_k][a_m + j * 32] = ar[j];
        Bs[b_k + 0][b_n] = br.x;
        Bs[b_k + 1][b_n] = br.y;
        Bs[b_k + 2][b_n] = br.z;
        Bs[b_k + 3][b_n] = br.w;
        __syncthreads();

        if (kt + 1 < K1 / 8) load_tile(kt + 1);

#pragma unroll
        for (int kk = 0; kk < 8; ++kk) {
            float4 a0 = *reinterpret_cast<const float4*>(&As[kk][ty * 4]);
            float4 a1 = *reinterpret_cast<const float4*>(&As[kk][64 + ty * 4]);
            float4 b0 = *reinterpret_cast<const float4*>(&Bs[kk][tx * 4]);
            float4 b1v = *reinterpret_cast<const float4*>(&Bs[kk][64 + tx * 4]);
            float av[8] = {a0.x, a0.y, a0.z, a0.w, a1.x, a1.y, a1.z, a1.w};
            float bv[8] = {b0.x, b0.y, b0.z, b0.w, b1v.x, b1v.y, b1v.z, b1v.w};
#pragma unroll
            for (int i = 0; i < 8; ++i)
#pragma unroll
                for (int j = 0; j < 8; ++j)
                    acc[i][j] = fmaf(av[i], bv[j], acc[i][j]);
        }
        __syncthreads();
    }

    float bias0[4], bias1[4];
#pragma unroll
    for (int c = 0; c < 4; ++c) {
        bias0[c] = __ldg(b1 + n_base + tx * 4 + c);
        bias1[c] = __ldg(b1 + n_base + 64 + tx * 4 + c);
    }

#pragma unroll
    for (int ri = 0; ri < 8; ++ri) {
        int row_local = (ri < 4) ? (ty * 4 + ri) : (64 + ty * 4 + (ri - 4));
        int m = m_base + row_local;
        if (m >= M1) continue;
        float* outp = &g_mid[(size_t)m * DIM + n_base];

        float4 v0, v1;
        float* pv0 = reinterpret_cast<float*>(&v0);
        float* pv1 = reinterpret_cast<float*>(&v1);
#pragma unroll
        for (int c = 0; c < 4; ++c) {
            float x0 = acc[ri][c]     + bias0[c];
            float x1 = acc[ri][4 + c] + bias1[c];
            pv0[c] = fminf(fmaxf(x0, 0.f), 6.f);
            pv1[c] = fminf(fmaxf(x1, 0.f), 6.f);
        }
        *reinterpret_cast<float4*>(outp + tx * 4)      = v0;
        *reinterpret_cast<float4*>(outp + 64 + tx * 4) = v1;
    }
#endif  // TC05
}

// ---------------------------------------------------------------------------
// Kernel 2: conv1x1 (512->120) + bias (fp32 SIMT, ~164us)
// ---------------------------------------------------------------------------
__global__ __launch_bounds__(256)
void conv1x1_kernel(const float* __restrict__ w2,
                    const float* __restrict__ b2,
                    float* __restrict__ out)
{
    __shared__ float As[16][64];
    __shared__ float Bs[16][128];

    const int tid    = threadIdx.x;
    const int m_base = blockIdx.x * 64;

    const int a_p  = tid >> 2;
    const int a_kq = (tid & 3) * 4;
    const int a_m  = m_base + a_p;
    const bool a_ok = (a_m < M1);

    const int b_co = tid >> 1;
    const int b_kq = (tid & 1) * 8;
    const bool b_ok = (b_co < COUT);

    const int ty = tid >> 4;
    const int tx = tid & 15;

    float acc[4][8];
#pragma unroll
    for (int i = 0; i < 4; ++i)
#pragma unroll
        for (int j = 0; j < 8; ++j) acc[i][j] = 0.f;

    for (int kt = 0; kt < DIM / 16; ++kt) {
        float4 av = make_float4(0.f, 0.f, 0.f, 0.f);
        if (a_ok)
            av = *reinterpret_cast<const float4*>(
                     &g_mid[(size_t)a_m * DIM + kt * 16 + a_kq]);
        As[a_kq + 0][a_p] = av.x;
        As[a_kq + 1][a_p] = av.y;
        As[a_kq + 2][a_p] = av.z;
        As[a_kq + 3][a_p] = av.w;

        float4 bv0 = make_float4(0.f, 0.f, 0.f, 0.f);
        float4 bv1 = make_float4(0.f, 0.f, 0.f, 0.f);
        if (b_ok) {
            const float* wp = w2 + (size_t)b_co * DIM + kt * 16 + b_kq;
            bv0 = *reinterpret_cast<const float4*>(wp);
            bv1 = *reinterpret_cast<const float4*>(wp + 4);
        }
        Bs[b_kq + 0][b_co] = bv0.x;
        Bs[b_kq + 1][b_co] = bv0.y;
        Bs[b_kq + 2][b_co] = bv0.z;
        Bs[b_kq + 3][b_co] = bv0.w;
        Bs[b_kq + 4][b_co] = bv1.x;
        Bs[b_kq + 5][b_co] = bv1.y;
        Bs[b_kq + 6][b_co] = bv1.z;
        Bs[b_kq + 7][b_co] = bv1.w;
        __syncthreads();

#pragma unroll
        for (int kk = 0; kk < 16; ++kk) {
            float4 a0 = *reinterpret_cast<const float4*>(&As[kk][ty * 4]);
            float4 b0 = *reinterpret_cast<const float4*>(&Bs[kk][tx * 4]);
            float4 b1v = *reinterpret_cast<const float4*>(&Bs[kk][64 + tx * 4]);
            float av4[4] = {a0.x, a0.y, a0.z, a0.w};
            float bv8[8] = {b0.x, b0.y, b0.z, b0.w, b1v.x, b1v.y, b1v.z, b1v.w};
#pragma unroll
            for (int i = 0; i < 4; ++i)
#pragma unroll
                for (int j = 0; j < 8; ++j)
                    acc[i][j] = fmaf(av4[i], bv8[j], acc[i][j]);
        }
        __syncthreads();
    }

    float bias0[4], bias1[4];
#pragma unroll
    for (int c = 0; c < 4; ++c) {
        bias0[c] = __ldg(b2 + tx * 4 + c);
        int n1 = 64 + tx * 4 + c;
        bias1[c] = (n1 < COUT) ? __ldg(b2 + n1) : 0.f;
    }
    const bool chunk1_ok = (64 + tx * 4 + 3) < COUT;

#pragma unroll
    for (int i = 0; i < 4; ++i) {
        int m = m_base + ty * 4 + i;
        if (m >= M1) continue;
        float* op = out + (size_t)m * COUT;

        float4 v0;
        float* pv0 = reinterpret_cast<float*>(&v0);
#pragma unroll
        for (int c = 0; c < 4; ++c) pv0[c] = acc[i][c] + bias0[c];
        *reinterpret_cast<float4*>(op + tx * 4) = v0;

        if (chunk1_ok) {
            float4 v1;
            float* pv1 = reinterpret_cast<float*>(&v1);
#pragma unroll
            for (int c = 0; c < 4; ++c) pv1[c] = acc[i][4 + c] + bias1[c];
            *reinterpret_cast<float4*>(op + 64 + tx * 4) = v1;
        }
    }
}

// ---------------------------------------------------------------------------
// Launch: fmap, w1, b1, w2, b2 -> out fp32 [43808][120]
// ---------------------------------------------------------------------------
extern "C" void kernel_launch(void* const* d_in, const int* in_sizes, int n_in,
                              void* d_out, int out_size)
{
    const float* fmap = (const float*)d_in[0];
    const float* w1   = (const float*)d_in[1];
    const float* b1   = (const float*)d_in[2];
    const float* w2   = (const float*)d_in[3];
    const float* b2   = (const float*)d_in[4];
    float* out = (float*)d_out;

    dim3 gtp((HW + 31) / 32, CIN / 32, BATCH);   // (43, 32, 32)
    prep_fmap_kernel<<<gtp, dim3(32, 8)>>>(fmap);
    prep_w1_kernel<<<(DIM * 9 * CIN + 255) / 256, 256>>>(w1);

    cudaFuncSetAttribute(conv3x3_mma_kernel,
                         cudaFuncAttributeMaxDynamicSharedMemorySize, SMEM_DYN);
    dim3 grid1((M1 + BM - 1) / BM, DIM / BN);    // (343, 4)
    conv3x3_mma_kernel<<<grid1, 256, SMEM_DYN>>>(fmap, w1, b1);

    dim3 grid2((M1 + 63) / 64);                  // 685
    conv1x1_kernel<<<grid2, 256>>>(w2, b2, out);
}